// round 1
// baseline (speedup 1.0000x reference)
#include <cuda_runtime.h>
#include <math.h>

// Problem constants (fixed by the dataset: r is [16, 2048, 3] fp32)
#define BATCH   16
#define NCC     2
#define NPTS    1024              // points per MST problem (2048 / NCC)
#define NPROB   (BATCH * NCC)     // 32 independent MST problems
#define THREADS 256
#define PPT     (NPTS / THREADS)  // 4 points per thread
#define NW      (THREADS / 32)    // 8 warps

__device__ float g_partials[NPROB];

__device__ __forceinline__ float warp_sum(float v) {
#pragma unroll
    for (int o = 16; o; o >>= 1) v += __shfl_xor_sync(0xffffffffu, v, o);
    return v;
}

__global__ __launch_bounds__(THREADS, 1)
void topo_mst_kernel(const float* __restrict__ r)
{
    // Shared: broadcast copy of normalized points + reduction scratch
    __shared__ float px[NPTS], py[NPTS], pz[NPTS];
    __shared__ float redbuf[3][NW];
    __shared__ unsigned s_bits[2][NW];   // double-buffered cross-warp argmin
    __shared__ int      s_idx[2][NW];

    const int prob   = blockIdx.x;       // 0..31
    const int sample = prob >> 1;
    const int chunk  = prob & 1;
    const int tid    = threadIdx.x;
    const int lane   = tid & 31;
    const int wid    = tid >> 5;

    const float* base = r + ((size_t)sample * (NCC * NPTS) + (size_t)chunk * NPTS) * 3;

    // ---- Load points (strided: thread t owns points t, t+256, t+512, t+768) ----
    float lx[PPT], ly[PPT], lz[PPT];
    float sx = 0.f, sy = 0.f, sz = 0.f;
#pragma unroll
    for (int s = 0; s < PPT; s++) {
        int i = tid + s * THREADS;
        float x = base[3 * i + 0];
        float y = base[3 * i + 1];
        float z = base[3 * i + 2];
        lx[s] = x; ly[s] = y; lz[s] = z;
        sx += x; sy += y; sz += z;
    }

    // ---- Mean (per channel) ----
    sx = warp_sum(sx); sy = warp_sum(sy); sz = warp_sum(sz);
    if (lane == 0) { redbuf[0][wid] = sx; redbuf[1][wid] = sy; redbuf[2][wid] = sz; }
    __syncthreads();
    float mx = 0.f, my = 0.f, mz = 0.f;
#pragma unroll
    for (int w = 0; w < NW; w++) { mx += redbuf[0][w]; my += redbuf[1][w]; mz += redbuf[2][w]; }
    mx *= (1.0f / NPTS); my *= (1.0f / NPTS); mz *= (1.0f / NPTS);
    __syncthreads();

    // ---- Variance (per channel) ----
    float vx = 0.f, vy = 0.f, vz = 0.f;
#pragma unroll
    for (int s = 0; s < PPT; s++) {
        float dx = lx[s] - mx, dy = ly[s] - my, dz = lz[s] - mz;
        vx = fmaf(dx, dx, vx); vy = fmaf(dy, dy, vy); vz = fmaf(dz, dz, vz);
    }
    vx = warp_sum(vx); vy = warp_sum(vy); vz = warp_sum(vz);
    if (lane == 0) { redbuf[0][wid] = vx; redbuf[1][wid] = vy; redbuf[2][wid] = vz; }
    __syncthreads();
    vx = 0.f; vy = 0.f; vz = 0.f;
#pragma unroll
    for (int w = 0; w < NW; w++) { vx += redbuf[0][w]; vy += redbuf[1][w]; vz += redbuf[2][w]; }
    const float inx = 1.0f / (sqrtf(vx * (1.0f / NPTS)) + 1e-8f);
    const float iny = 1.0f / (sqrtf(vy * (1.0f / NPTS)) + 1e-8f);
    const float inz = 1.0f / (sqrtf(vz * (1.0f / NPTS)) + 1e-8f);

    // ---- Normalize into registers + shared broadcast copy ----
#pragma unroll
    for (int s = 0; s < PPT; s++) {
        int i = tid + s * THREADS;
        lx[s] = (lx[s] - mx) * inx;
        ly[s] = (ly[s] - my) * iny;
        lz[s] = (lz[s] - mz) * inz;
        px[i] = lx[s]; py[i] = ly[s]; pz[i] = lz[s];
    }
    __syncthreads();

    // ---- Prim's MST ----
    const float INF  = __int_as_float(0x7f800000);
    const float NANF = __int_as_float(0x7fc00000);

    float x0 = px[0], y0 = py[0], z0 = pz[0];
    float mind[PPT];
#pragma unroll
    for (int s = 0; s < PPT; s++) {
        float dx = lx[s] - x0, dy = ly[s] - y0, dz = lz[s] - z0;
        mind[s] = fmaf(dx, dx, fmaf(dy, dy, dz * dz));
    }
    if (tid == 0) {   // point 0 is the root: visited
        mind[0] = INF;
        lx[0] = NANF; ly[0] = NANF; lz[0] = NANF;   // NaN coords => fminf never updates
    }

    float total = 0.0f;
    for (int it = 0; it < NPTS - 1; ++it) {
        const int buf = it & 1;

        // thread-local argmin over PPT slots (static indices only)
        float bv = mind[0]; int bi = tid;
#pragma unroll
        for (int s = 1; s < PPT; s++) {
            if (mind[s] < bv) { bv = mind[s]; bi = tid + s * THREADS; }
        }

        // warp argmin: dist bits are order-preserving uints (non-negative floats)
        unsigned bits = __float_as_uint(bv);
        unsigned wmin = __reduce_min_sync(0xffffffffu, bits);
        unsigned ball = __ballot_sync(0xffffffffu, bits == wmin);
        int src  = __ffs(ball) - 1;
        int widx = __shfl_sync(0xffffffffu, bi, src);

        if (lane == 0) { s_bits[buf][wid] = wmin; s_idx[buf][wid] = widx; }
        __syncthreads();   // single barrier per iteration (buffers alternate)

        // cross-warp argmin (all threads, redundantly — cheap, no 2nd barrier)
        unsigned gb = s_bits[buf][0]; int gj = s_idx[buf][0];
#pragma unroll
        for (int w = 1; w < NW; w++) {
            unsigned b = s_bits[buf][w];
            if (b < gb) { gb = b; gj = s_idx[buf][w]; }
        }
        total += __uint_as_float(gb);

        // fetch new tree node's coords (broadcast LDS)
        float xj = px[gj], yj = py[gj], zj = pz[gj];

        // mark the chosen point visited in its owner's registers
#pragma unroll
        for (int s = 0; s < PPT; s++) {
            if (gj == tid + s * THREADS) {
                mind[s] = INF;
                lx[s] = NANF; ly[s] = NANF; lz[s] = NANF;
            }
        }

        // relax: NaN coords make d2 NaN; fminf(mind, NaN) == mind => visited stay INF
#pragma unroll
        for (int s = 0; s < PPT; s++) {
            float dx = lx[s] - xj, dy = ly[s] - yj, dz = lz[s] - zj;
            float d2 = fmaf(dx, dx, fmaf(dy, dy, dz * dz));
            mind[s] = fminf(mind[s], d2);
        }
    }

    if (tid == 0) g_partials[prob] = total;
}

__global__ void finalize_kernel(float* __restrict__ out)
{
    float v = g_partials[threadIdx.x];
#pragma unroll
    for (int o = 16; o; o >>= 1) v += __shfl_xor_sync(0xffffffffu, v, o);
    if (threadIdx.x == 0) out[0] = v * (1.0f / NPROB);
}

extern "C" void kernel_launch(void* const* d_in, const int* in_sizes, int n_in,
                              void* d_out, int out_size)
{
    const float* r = (const float*)d_in[0];
    float* out = (float*)d_out;
    topo_mst_kernel<<<NPROB, THREADS>>>(r);
    finalize_kernel<<<1, 32>>>(out);
}

// round 2
// speedup vs baseline: 1.6433x; 1.6433x over previous
#include <cuda_runtime.h>
#include <math.h>

// Dataset-fixed shapes: r is [16, 2048, 3] fp32
#define BATCH   16
#define NCC     2
#define NPTS    1024              // points per MST problem
#define NPROB   (BATCH * NCC)     // 32 independent MST problems
#define THREADS 256
#define PPT     (NPTS / THREADS)  // 4 points per thread
#define NW      (THREADS / 32)    // 8 warps

__device__ float g_partials[NPROB];

__device__ __forceinline__ float warp_sum(float v) {
#pragma unroll
    for (int o = 16; o; o >>= 1) v += __shfl_xor_sync(0xffffffffu, v, o);
    return v;
}

__device__ __forceinline__ unsigned um(unsigned a, unsigned b) { return a < b ? a : b; }

// Pack: high 22 bits = float bits of squared distance (low 10 mantissa bits
// truncated), low 10 bits = point index. Unsigned order == (dist, idx) order.
#define PK_MASK 0xFFFFFC00u

__global__ __launch_bounds__(THREADS, 1)
void topo_mst_kernel(const float* __restrict__ r)
{
    __shared__ float4 pts[NPTS];                     // normalized points (w unused)
    __shared__ float redbuf[3][NW];
    __shared__ alignas(16) unsigned s_pk[2][NW];     // double-buffered warp mins

    const int prob   = blockIdx.x;
    const int sample = prob >> 1;
    const int chunk  = prob & 1;
    const int tid    = threadIdx.x;
    const int lane   = tid & 31;
    const int wid    = tid >> 5;

    const float* base = r + ((size_t)sample * (NCC * NPTS) + (size_t)chunk * NPTS) * 3;

    // ---- Load (thread t owns points t, t+256, t+512, t+768) ----
    float lx[PPT], ly[PPT], lz[PPT];
    float sx = 0.f, sy = 0.f, sz = 0.f;
#pragma unroll
    for (int s = 0; s < PPT; s++) {
        int i = tid + s * THREADS;
        float x = base[3 * i + 0];
        float y = base[3 * i + 1];
        float z = base[3 * i + 2];
        lx[s] = x; ly[s] = y; lz[s] = z;
        sx += x; sy += y; sz += z;
    }

    // ---- Mean ----
    sx = warp_sum(sx); sy = warp_sum(sy); sz = warp_sum(sz);
    if (lane == 0) { redbuf[0][wid] = sx; redbuf[1][wid] = sy; redbuf[2][wid] = sz; }
    __syncthreads();
    float mx = 0.f, my = 0.f, mz = 0.f;
#pragma unroll
    for (int w = 0; w < NW; w++) { mx += redbuf[0][w]; my += redbuf[1][w]; mz += redbuf[2][w]; }
    mx *= (1.0f / NPTS); my *= (1.0f / NPTS); mz *= (1.0f / NPTS);
    __syncthreads();

    // ---- Variance ----
    float vx = 0.f, vy = 0.f, vz = 0.f;
#pragma unroll
    for (int s = 0; s < PPT; s++) {
        float dx = lx[s] - mx, dy = ly[s] - my, dz = lz[s] - mz;
        vx = fmaf(dx, dx, vx); vy = fmaf(dy, dy, vy); vz = fmaf(dz, dz, vz);
    }
    vx = warp_sum(vx); vy = warp_sum(vy); vz = warp_sum(vz);
    if (lane == 0) { redbuf[0][wid] = vx; redbuf[1][wid] = vy; redbuf[2][wid] = vz; }
    __syncthreads();
    vx = 0.f; vy = 0.f; vz = 0.f;
#pragma unroll
    for (int w = 0; w < NW; w++) { vx += redbuf[0][w]; vy += redbuf[1][w]; vz += redbuf[2][w]; }
    const float inx = 1.0f / (sqrtf(vx * (1.0f / NPTS)) + 1e-8f);
    const float iny = 1.0f / (sqrtf(vy * (1.0f / NPTS)) + 1e-8f);
    const float inz = 1.0f / (sqrtf(vz * (1.0f / NPTS)) + 1e-8f);

    // ---- Normalize into registers + shared float4 broadcast copy ----
#pragma unroll
    for (int s = 0; s < PPT; s++) {
        int i = tid + s * THREADS;
        lx[s] = (lx[s] - mx) * inx;
        ly[s] = (ly[s] - my) * iny;
        lz[s] = (lz[s] - mz) * inz;
        pts[i] = make_float4(lx[s], ly[s], lz[s], 0.0f);
    }
    __syncthreads();

    // ---- Prim's MST ----
    const float    INF_F   = __int_as_float(0x7f800000);
    const unsigned VISITED = 0xFFFFFFFFu;

    float4 p0 = pts[0];
    unsigned pk[PPT];
#pragma unroll
    for (int s = 0; s < PPT; s++) {
        float dx = lx[s] - p0.x, dy = ly[s] - p0.y, dz = lz[s] - p0.z;
        float d2 = fmaf(dx, dx, fmaf(dy, dy, dz * dz));
        pk[s] = (__float_as_uint(d2) & PK_MASK) | (unsigned)(tid + s * THREADS);
    }
    if (tid == 0) {     // root is visited; INF coords make its future d2 = +inf
        pk[0] = VISITED;
        lx[0] = INF_F; ly[0] = INF_F; lz[0] = INF_F;
    }

    float total = 0.0f;
    for (int it = 0; it < NPTS - 1; ++it) {
        const int buf = it & 1;

        // thread-local min (3 IMNMX) + warp REDUX carries value AND index
        unsigned lm = um(um(pk[0], pk[1]), um(pk[2], pk[3]));
        unsigned wm = __reduce_min_sync(0xffffffffu, lm);
        if (lane == 0) s_pk[buf][wid] = wm;
        __syncthreads();   // one barrier per iteration (double-buffered exchange)

        // cross-warp min: 2x LDS.128 + 7 IMNMX (depth 3)
        const uint4* q = reinterpret_cast<const uint4*>(s_pk[buf]);
        uint4 a = q[0], b = q[1];
        unsigned m0 = um(a.x, a.y), m1 = um(a.z, a.w);
        unsigned m2 = um(b.x, b.y), m3 = um(b.z, b.w);
        unsigned g  = um(um(m0, m1), um(m2, m3));

        int gj = (int)(g & 1023u);
        total += __uint_as_float(g & PK_MASK);

        float4 pj = pts[gj];   // single LDS.128 broadcast

        // mark chosen point visited in its owner's registers
#pragma unroll
        for (int s = 0; s < PPT; s++) {
            if (gj == tid + s * THREADS) {
                pk[s] = VISITED;
                lx[s] = INF_F; ly[s] = INF_F; lz[s] = INF_F;
            }
        }

        // relax: INF coords -> d2 = +inf -> packed above every finite value
#pragma unroll
        for (int s = 0; s < PPT; s++) {
            float dx = lx[s] - pj.x, dy = ly[s] - pj.y, dz = lz[s] - pj.z;
            float d2 = fmaf(dx, dx, fmaf(dy, dy, dz * dz));
            unsigned cand = (__float_as_uint(d2) & PK_MASK) | (unsigned)(tid + s * THREADS);
            pk[s] = um(pk[s], cand);
        }
    }

    if (tid == 0) g_partials[prob] = total;
}

__global__ void finalize_kernel(float* __restrict__ out)
{
    float v = g_partials[threadIdx.x];
#pragma unroll
    for (int o = 16; o; o >>= 1) v += __shfl_xor_sync(0xffffffffu, v, o);
    if (threadIdx.x == 0) out[0] = v * (1.0f / NPROB);
}

extern "C" void kernel_launch(void* const* d_in, const int* in_sizes, int n_in,
                              void* d_out, int out_size)
{
    const float* r = (const float*)d_in[0];
    float* out = (float*)d_out;
    topo_mst_kernel<<<NPROB, THREADS>>>(r);
    finalize_kernel<<<1, 32>>>(out);
}